// round 1
// baseline (speedup 1.0000x reference)
#include <cuda_runtime.h>
#include <cstdint>

// ---------------- problem constants ----------------
#define BB      8
#define HEADS   4
#define NQ      3136
#define NKV     784
#define DH      32      // head dim
#define CC      128
#define TQ      128     // queries per CTA (attention)
#define TK      56      // kv tile (784 = 14*56)

typedef unsigned long long u64;

// ---------------- scratch (device globals; no allocation) ----------------
__device__ float g_q [BB * HEADS * NQ  * DH];   // (B,H,N,32)
__device__ float g_k [BB * HEADS * NKV * DH];   // (B,H,Nkv,32)
__device__ float g_v [BB * HEADS * NKV * DH];
__device__ float g_xr[BB * NKV * CC];           // spatially reduced tokens
__device__ float g_ao[BB * NQ  * CC];           // attention output (B,N,C)

// ---------------- f32x2 packed helpers (Blackwell FFMA2) ----------------
__device__ __forceinline__ u64 pack2(float x, float y) {
    u64 r; asm("mov.b64 %0, {%1, %2};" : "=l"(r) : "f"(x), "f"(y)); return r;
}
__device__ __forceinline__ void unpack2(u64 v, float& x, float& y) {
    asm("mov.b64 {%0, %1}, %2;" : "=f"(x), "=f"(y) : "l"(v));
}
__device__ __forceinline__ u64 fma2(u64 a, u64 b, u64 c) {
    u64 d; asm("fma.rn.f32x2 %0, %1, %2, %3;" : "=l"(d) : "l"(a), "l"(b), "l"(c)); return d;
}
__device__ __forceinline__ u64 mul2(u64 a, u64 b) {
    u64 d; asm("mul.rn.f32x2 %0, %1, %2;" : "=l"(d) : "l"(a), "l"(b)); return d;
}

// ---------------- projection GEMM: Y = X(Mx128) @ W(128x128) + b ----------------
// CTA tile 64 rows x 128 cols, k-chunks of 32. Thread tile 8x4.
// swizzle=1: output scattered to (B,H,rows,32) head-major layout.
__global__ __launch_bounds__(256) void proj_kernel(
    const float* __restrict__ X, const float* __restrict__ W,
    const float* __restrict__ bias, float* __restrict__ Y,
    int M, int RPB, int swizzle)
{
    __shared__ float Xs[64][32];
    __shared__ float Ws[32][128];

    const int tid   = threadIdx.x;
    const int rowb  = blockIdx.x * 64;
    const int col_t = tid & 31;   // 0..31 -> 4 cols each
    const int row_t = tid >> 5;   // 0..7  -> 8 rows each

    float acc[8][4];
#pragma unroll
    for (int r = 0; r < 8; r++) { acc[r][0]=0.f; acc[r][1]=0.f; acc[r][2]=0.f; acc[r][3]=0.f; }

    for (int kc = 0; kc < 128; kc += 32) {
        __syncthreads();
#pragma unroll
        for (int i = 0; i < 8; i++) {          // X tile: 64x32
            int idx = tid + i * 256;
            int r = idx >> 5, kk = idx & 31;
            Xs[r][kk] = X[(size_t)(rowb + r) * CC + kc + kk];
        }
#pragma unroll
        for (int i = 0; i < 16; i++) {         // W tile: 32x128
            int idx = tid + i * 256;
            int kk = idx >> 7, cc2 = idx & 127;
            Ws[kk][cc2] = W[(size_t)(kc + kk) * CC + cc2];
        }
        __syncthreads();
#pragma unroll
        for (int kk = 0; kk < 32; kk++) {
            float4 wv = *(const float4*)&Ws[kk][col_t * 4];
#pragma unroll
            for (int r = 0; r < 8; r++) {
                float xv = Xs[row_t * 8 + r][kk];
                acc[r][0] += xv * wv.x;
                acc[r][1] += xv * wv.y;
                acc[r][2] += xv * wv.z;
                acc[r][3] += xv * wv.w;
            }
        }
    }

    const int col0 = col_t * 4;
    float4 bv = *(const float4*)&bias[col0];
#pragma unroll
    for (int r = 0; r < 8; r++) {
        int row = rowb + row_t * 8 + r;
        if (row >= M) continue;
        float4 o;
        o.x = acc[r][0] + bv.x; o.y = acc[r][1] + bv.y;
        o.z = acc[r][2] + bv.z; o.w = acc[r][3] + bv.w;
        if (swizzle) {
            int b = row / RPB, n = row % RPB;
            int h = col0 >> 5, d = col0 & 31;
            *(float4*)&Y[(((size_t)(b * HEADS + h) * RPB + n)) * DH + d] = o;
        } else {
            *(float4*)&Y[(size_t)row * CC + col0] = o;
        }
    }
}

// ---------------- spatial reduction: depthwise 2x2 stride-2 conv + BN (eval) ----------------
__global__ void sr_conv_kernel(
    const float* __restrict__ x, const float* __restrict__ cw, const float* __restrict__ cb,
    const float* __restrict__ gamma, const float* __restrict__ beta,
    const float* __restrict__ mean, const float* __restrict__ var,
    float* __restrict__ xr)
{
    int t = blockIdx.x * blockDim.x + threadIdx.x;
    if (t >= BB * NKV * CC) return;
    int c = t & (CC - 1);
    int p = (t >> 7) % NKV;
    int b = t / (NKV * CC);
    int oy = p / 28, ox = p % 28;

    const float* xb = x + (size_t)b * NQ * CC;
    float s = 0.f;
#pragma unroll
    for (int i = 0; i < 2; i++)
#pragma unroll
        for (int j = 0; j < 2; j++)
            s += xb[(size_t)((2 * oy + i) * 56 + (2 * ox + j)) * CC + c] * cw[c * 4 + i * 2 + j];
    s += cb[c];
    float iv = gamma[c] * rsqrtf(var[c] + 1e-5f);
    xr[t] = s * iv + (beta[c] - mean[c] * iv);
}

// ---------------- fused flash attention (one (b,h) per CTA-column, 128 queries/CTA) --------
__global__ __launch_bounds__(128) void attn_kernel(
    const float* __restrict__ q, const float* __restrict__ k, const float* __restrict__ v,
    const float* __restrict__ relpos, float* __restrict__ out)
{
    __shared__ __align__(16) float Ks[TK][DH];
    __shared__ __align__(16) float Vs[TK][DH];
    __shared__ float Bsm[TQ][TK + 1];   // stride 57 -> conflict-free column reads

    const int b  = blockIdx.z;
    const int h  = blockIdx.y;
    const int qt = blockIdx.x;
    const int tid = threadIdx.x;
    const int n = qt * TQ + tid;
    const bool valid = (n < NQ);
    const float scale = 0.17677669529663687f;  // 32^-0.5

    // load q row (pre-scaled), packed as 16 f32x2
    u64 ql2[16];
    {
        const float* qrow = q + ((size_t)(b * HEADS + h) * NQ + (valid ? n : 0)) * DH;
#pragma unroll
        for (int i = 0; i < 8; i++) {
            float4 t4 = *(const float4*)(qrow + i * 4);
            ql2[2 * i]     = pack2(t4.x * scale, t4.y * scale);
            ql2[2 * i + 1] = pack2(t4.z * scale, t4.w * scale);
        }
    }

    float m = -1e30f, l = 0.f;
    u64 acc2[16];
#pragma unroll
    for (int i = 0; i < 16; i++) acc2[i] = pack2(0.f, 0.f);

    const float* kb = k + (size_t)(b * HEADS + h) * NKV * DH;
    const float* vb = v + (size_t)(b * HEADS + h) * NKV * DH;
    const float* rp = relpos + (size_t)h * NQ * NKV;
    const int qbase = qt * TQ;

    for (int kt = 0; kt < NKV; kt += TK) {
        __syncthreads();
        // cooperative K/V tile load (coalesced)
#pragma unroll 2
        for (int idx = tid; idx < TK * DH; idx += 128) {
            int r = idx >> 5, d = idx & 31;
            Ks[r][d] = kb[(size_t)(kt + r) * DH + d];
            Vs[r][d] = vb[(size_t)(kt + r) * DH + d];
        }
        // cooperative bias tile load (coalesced); incremental div-free indexing
        {
            int r = tid / TK, c = tid % TK;
#pragma unroll 1
            for (int it = 0; it < TK; it++) {      // 128*56/128 = 56 iterations
                int qn = qbase + r;
                Bsm[r][c] = (qn < NQ) ? rp[(size_t)qn * NKV + kt + c] : 0.f;
                r += 2; c += 16;
                if (c >= TK) { c -= TK; r += 1; }
            }
        }
        __syncthreads();

        if (valid) {
#pragma unroll 1
            for (int mm = 0; mm < TK; mm++) {
                const u64* krow = (const u64*)Ks[mm];
                u64 s2 = pack2(Bsm[tid][mm], 0.f);
#pragma unroll
                for (int i = 0; i < 16; i++) s2 = fma2(ql2[i], krow[i], s2);
                float sx, sy; unpack2(s2, sx, sy);
                float s = sx + sy;

                if (s > m) {
                    float corr = __expf(m - s);
                    u64 c2 = pack2(corr, corr);
                    l *= corr;
#pragma unroll
                    for (int i = 0; i < 16; i++) acc2[i] = mul2(acc2[i], c2);
                    m = s;
                }
                float p = __expf(s - m);
                l += p;
                u64 p2 = pack2(p, p);
                const u64* vrow = (const u64*)Vs[mm];
#pragma unroll
                for (int i = 0; i < 16; i++) acc2[i] = fma2(p2, vrow[i], acc2[i]);
            }
        }
    }

    if (valid) {
        float inv = 1.f / l;
        float* orow = out + ((size_t)(b * NQ + n)) * CC + h * DH;
#pragma unroll
        for (int i = 0; i < 8; i++) {
            float x0, x1, x2, x3;
            unpack2(acc2[2 * i], x0, x1);
            unpack2(acc2[2 * i + 1], x2, x3);
            float4 o; o.x = x0 * inv; o.y = x1 * inv; o.z = x2 * inv; o.w = x3 * inv;
            *(float4*)(orow + i * 4) = o;
        }
    }
}

// ---------------- launch ----------------
extern "C" void kernel_launch(void* const* d_in, const int* in_sizes, int n_in,
                              void* d_out, int out_size)
{
    const float* x      = (const float*)d_in[0];
    const float* relpos = (const float*)d_in[1];
    const float* Wq     = (const float*)d_in[2];
    const float* bq     = (const float*)d_in[3];
    const float* Wk     = (const float*)d_in[4];
    const float* bk     = (const float*)d_in[5];
    const float* Wv     = (const float*)d_in[6];
    const float* bv     = (const float*)d_in[7];
    const float* cw     = (const float*)d_in[8];
    const float* cb     = (const float*)d_in[9];
    const float* gamma  = (const float*)d_in[10];
    const float* beta   = (const float*)d_in[11];
    const float* mean   = (const float*)d_in[12];
    const float* var    = (const float*)d_in[13];
    const float* Wp     = (const float*)d_in[14];
    const float* bp     = (const float*)d_in[15];
    float* out = (float*)d_out;

    float *q, *k, *v, *xr, *ao;
    cudaGetSymbolAddress((void**)&q,  g_q);
    cudaGetSymbolAddress((void**)&k,  g_k);
    cudaGetSymbolAddress((void**)&v,  g_v);
    cudaGetSymbolAddress((void**)&xr, g_xr);
    cudaGetSymbolAddress((void**)&ao, g_ao);

    // 1) q projection (head-swizzled)
    proj_kernel<<<(BB * NQ) / 64, 256>>>(x, Wq, bq, q, BB * NQ, NQ, 1);
    // 2) spatial reduction conv + BN
    sr_conv_kernel<<<(BB * NKV * CC + 255) / 256, 256>>>(x, cw, cb, gamma, beta, mean, var, xr);
    // 3/4) k, v projections (head-swizzled)
    proj_kernel<<<(BB * NKV) / 64, 256>>>(xr, Wk, bk, k, BB * NKV, NKV, 1);
    proj_kernel<<<(BB * NKV) / 64, 256>>>(xr, Wv, bv, v, BB * NKV, NKV, 1);
    // 5) fused attention with online softmax
    dim3 ag((NQ + TQ - 1) / TQ, HEADS, BB);
    attn_kernel<<<ag, 128>>>(q, k, v, relpos, ao);
    // 6) output projection
    proj_kernel<<<(BB * NQ) / 64, 256>>>(ao, Wp, bp, out, BB * NQ, NQ, 0);
}